// round 1
// baseline (speedup 1.0000x reference)
#include <cuda_runtime.h>
#include <math.h>

#define NN 10000
#define NE 160000
#define WARPS_B 12
#define THREADS_B (WARPS_B*32)
#define GRID_B 296

// ---------------- scratch (static device allocations only) ----------------
static __device__ float g_qt0[NN*8];    // w_sim0^T q0 * cs
static __device__ float g_qt1[NN*12];   // w_sim1^T q1 * cs/sqrt(3)
static __device__ float g_maxv[NN];
static __device__ float g_den[NN];
static __device__ float g_logits[NE];   // logits, then exp()
static __device__ float g_vals[NE*20];

__device__ __forceinline__ void atomicMaxFloat(float* addr, float v){
    if (v >= 0.f) atomicMax((int*)addr, __float_as_int(v));
    else          atomicMin((unsigned int*)addr, __float_as_uint(v));
}

__device__ __forceinline__ float wsum(float v){
    #pragma unroll
    for (int o=16;o;o>>=1) v += __shfl_down_sync(0xffffffffu, v, o);
    return v;
}

// ---------------- kernel A: per-node query transform + init ----------------
__global__ void k_prep(const float* __restrict__ x,
                       const float* __restrict__ wq0, const float* __restrict__ wq1,
                       const float* __restrict__ ws0, const float* __restrict__ ws1,
                       float* __restrict__ out)
{
    int i = blockIdx.x*blockDim.x + threadIdx.x;
    if (i >= NN) return;
    const float* xr = x + (size_t)i*80;

    float q0[8];
    #pragma unroll
    for (int w=0;w<8;w++) q0[w]=0.f;
    #pragma unroll 4
    for (int u=0;u<32;u++){
        float xv = xr[u];
        #pragma unroll
        for (int w=0;w<8;w++) q0[w] = fmaf(xv, wq0[u*8+w], q0[w]);
    }
    #pragma unroll
    for (int w=0;w<8;w++) q0[w] *= 0.17677669529663687f;   // 1/sqrt(32)

    float q1[4][3];
    #pragma unroll
    for (int w=0;w<4;w++){ q1[w][0]=0.f; q1[w][1]=0.f; q1[w][2]=0.f; }
    #pragma unroll 4
    for (int u=0;u<16;u++){
        float xv0 = xr[32+u*3+0], xv1 = xr[32+u*3+1], xv2 = xr[32+u*3+2];
        #pragma unroll
        for (int w=0;w<4;w++){
            float wv = wq1[u*4+w];
            q1[w][0]=fmaf(xv0,wv,q1[w][0]);
            q1[w][1]=fmaf(xv1,wv,q1[w][1]);
            q1[w][2]=fmaf(xv2,wv,q1[w][2]);
        }
    }
    #pragma unroll
    for (int w=0;w<4;w++){ q1[w][0]*=0.25f; q1[w][1]*=0.25f; q1[w][2]*=0.25f; }

    // qt0[v] = cs * sum_u ws0[u,v] q0[u],  cs = 1/sqrt(80)
    const float CS  = 0.11180339887498949f;
    const float CS3 = 0.06454972243679028f;  // cs/sqrt(3)
    float qt0[8];
    #pragma unroll
    for (int v=0;v<8;v++) qt0[v]=0.f;
    #pragma unroll
    for (int u=0;u<8;u++){
        float qv = q0[u];
        #pragma unroll
        for (int v=0;v<8;v++) qt0[v] = fmaf(qv, ws0[u*8+v], qt0[v]);
    }
    float qt1[4][3];
    #pragma unroll
    for (int v=0;v<4;v++){ qt1[v][0]=0.f; qt1[v][1]=0.f; qt1[v][2]=0.f; }
    #pragma unroll
    for (int u=0;u<4;u++){
        #pragma unroll
        for (int v=0;v<4;v++){
            float wv = ws1[u*4+v];
            qt1[v][0]=fmaf(q1[u][0],wv,qt1[v][0]);
            qt1[v][1]=fmaf(q1[u][1],wv,qt1[v][1]);
            qt1[v][2]=fmaf(q1[u][2],wv,qt1[v][2]);
        }
    }
    #pragma unroll
    for (int v=0;v<8;v++) g_qt0[i*8+v] = CS * qt0[v];
    #pragma unroll
    for (int v=0;v<4;v++){
        g_qt1[i*12+v*3+0] = CS3*qt1[v][0];
        g_qt1[i*12+v*3+1] = CS3*qt1[v][1];
        g_qt1[i*12+v*3+2] = CS3*qt1[v][2];
    }
    g_maxv[i] = __int_as_float(0xff800000);   // -inf
    g_den[i]  = 0.f;
    #pragma unroll
    for (int j=0;j<20;j++) out[i*20+j] = 0.f;
}

// ---------------- kernel B: per-edge tensor-product net (K or V) ----------------
// lane = hidden index h; warp handles 2 edges at a time (kb2 load amortized 2x).
template<bool IS_K>
__global__ void __launch_bounds__(THREADS_B, 2) k_edge(
    const float* __restrict__ x, const float* __restrict__ pos,
    const float* __restrict__ w1g, const float* __restrict__ w2g,
    const int* __restrict__ ei)
{
    extern __shared__ float sm[];
    float* s_w2 = sm;                 // [32][580] padded
    float* s_w1 = sm + 32*580;        // [32][33]  padded
    float* s_ft = s_w1 + 32*33;       // per warp: 288 floats

    const int tid = threadIdx.x, lane = tid & 31, wp = tid >> 5;

    for (int i=tid; i<32*32; i+=THREADS_B) s_w1[(i>>5)*33 + (i&31)] = w1g[i];
    const float W2S = 0.02551551815399144f;   // (1/sqrt(48)) * (1/sqrt(32))
    for (int i=tid; i<32*576; i+=THREADS_B){
        int h = i/576, o = i - h*576;
        s_w2[h*580+o] = w2g[i]*W2S;
    }
    __syncthreads();

    float* ft = s_ft + wp*288;  // [rb 0..63][x0 64..127][x1 128..255][fd 256..287]

    for (int g = blockIdx.x*WARPS_B + wp; g < NE/2; g += gridDim.x*WARPS_B){
        float Y[2][3], cut[2];
        int srcs[2];
        #pragma unroll
        for (int ke=0; ke<2; ke++){
            int e = 2*g + ke;
            int s = ei[e], d = ei[NE+e];
            srcs[ke] = s;
            float vx = pos[3*s+0]-pos[3*d+0];
            float vy = pos[3*s+1]-pos[3*d+1];
            float vz = pos[3*s+2]-pos[3*d+2];
            float r2 = fmaf(vx,vx,fmaf(vy,vy,vz*vz)) + 1e-24f;
            float r  = sqrtf(r2);
            float ir = 1.f/r;
            Y[ke][0]=1.7320508075688772f*vx*ir;
            Y[ke][1]=1.7320508075688772f*vy*ir;
            Y[ke][2]=1.7320508075688772f*vz*ir;
            float t = 10.f*(1.f - r*0.4f);
            cut[ke] = (t>0.f) ? expf(-1.f/fmaxf(t,1e-12f)) : 0.f;
            // bessel basis (sqrt(32) scale cancels with /sqrt(32) of layer-1)
            ft[ke*32+lane] = 0.8944271909999159f * sinf((float)(lane+1)*1.2566370614359172f*r) * ir;
            const float* xr = x + (size_t)s*80;
            ft[64 + ke*32 + lane] = xr[lane];
            if (lane < 16){
                float* p = ft + 128 + ke*64 + lane*4;
                p[0]=xr[32+lane*3+0]; p[1]=xr[32+lane*3+1]; p[2]=xr[32+lane*3+2]; p[3]=0.f;
            }
        }
        __syncwarp();
        {   // f1dY[u] = (x1[u]·Y)/sqrt(3)
            int ke = lane>>4, u = lane&15;
            const float* p = ft + 128 + ke*64 + u*4;
            ft[256 + ke*16 + u] =
                fmaf(p[0],Y[ke][0],fmaf(p[1],Y[ke][1],p[2]*Y[ke][2])) * 0.5773502691896258f;
        }
        __syncwarp();

        // hidden layer: h_lane = silu(sum_i rb_i * w1[i,lane])
        float ha=0.f, hb=0.f;
        #pragma unroll 8
        for (int i=0;i<32;i++){
            float wv = s_w1[i*33+lane];
            ha = fmaf(ft[i],    wv, ha);
            hb = fmaf(ft[32+i], wv, hb);
        }
        float h0 = ha/(1.f+expf(-ha));
        float h1 = hb/(1.f+expf(-hb));

        const float* wr = s_w2 + lane*580;
        float a0[2][8], s01[2][4], v1[2][4][3];
        #pragma unroll
        for (int e=0;e<2;e++){
            #pragma unroll
            for (int w=0;w<8;w++) a0[e][w]=0.f;
            #pragma unroll
            for (int w=0;w<4;w++){ s01[e][w]=0.f; v1[e][w][0]=0.f; v1[e][w][1]=0.f; v1[e][w][2]=0.f; }
        }
        // paths 0e*0e->0e (off 0) and 0e*1o->1o (off 384), fused over x0
        #pragma unroll 4
        for (int u=0;u<32;u++){
            float b0 = ft[64+u], b1 = ft[96+u];
            float4 pA = *(const float4*)(wr + u*8);
            float4 pB = *(const float4*)(wr + u*8 + 4);
            float4 pC = *(const float4*)(wr + 384 + u*4);
            const float wv[8] = {pA.x,pA.y,pA.z,pA.w,pB.x,pB.y,pB.z,pB.w};
            #pragma unroll
            for (int w=0;w<8;w++){
                a0[0][w]=fmaf(wv[w],b0,a0[0][w]);
                a0[1][w]=fmaf(wv[w],b1,a0[1][w]);
            }
            const float wc[4]={pC.x,pC.y,pC.z,pC.w};
            #pragma unroll
            for (int w=0;w<4;w++){
                s01[0][w]=fmaf(wc[w],b0,s01[0][w]);
                s01[1][w]=fmaf(wc[w],b1,s01[1][w]);
            }
        }
        // path 1o*1o->0e (off 256), feature f1dY
        #pragma unroll 4
        for (int u=0;u<16;u++){
            float b0 = ft[256+u], b1 = ft[272+u];
            float4 pA = *(const float4*)(wr + 256 + u*8);
            float4 pB = *(const float4*)(wr + 256 + u*8 + 4);
            const float wv[8] = {pA.x,pA.y,pA.z,pA.w,pB.x,pB.y,pB.z,pB.w};
            #pragma unroll
            for (int w=0;w<8;w++){
                a0[0][w]=fmaf(wv[w],b0,a0[0][w]);
                a0[1][w]=fmaf(wv[w],b1,a0[1][w]);
            }
        }
        // path 1o*0e->1o (off 512), feature x1[u][m]
        #pragma unroll 4
        for (int u=0;u<16;u++){
            float4 wv4 = *(const float4*)(wr + 512 + u*4);
            const float wv[4]={wv4.x,wv4.y,wv4.z,wv4.w};
            float4 xa = *(const float4*)(ft + 128 + u*4);
            float4 xb = *(const float4*)(ft + 192 + u*4);
            const float xam[3]={xa.x,xa.y,xa.z};
            const float xbm[3]={xb.x,xb.y,xb.z};
            #pragma unroll
            for (int w=0;w<4;w++){
                #pragma unroll
                for (int m=0;m<3;m++){
                    v1[0][w][m]=fmaf(wv[w],xam[m],v1[0][w][m]);
                    v1[1][w][m]=fmaf(wv[w],xbm[m],v1[1][w][m]);
                }
            }
        }

        if (IS_K){
            float simv[2];
            #pragma unroll
            for (int ke=0;ke<2;ke++){
                const float* qt0 = g_qt0 + (size_t)srcs[ke]*8;
                const float* qt1 = g_qt1 + (size_t)srcs[ke]*12;
                float s = 0.f;
                #pragma unroll
                for (int w=0;w<8;w++) s = fmaf(qt0[w], a0[ke][w], s);
                #pragma unroll
                for (int w=0;w<4;w++){
                    #pragma unroll
                    for (int m=0;m<3;m++){
                        float k1 = fmaf(s01[ke][w], Y[ke][m], v1[ke][w][m]);
                        s = fmaf(qt1[w*3+m], k1, s);
                    }
                }
                simv[ke] = s * (ke ? h1 : h0);
            }
            simv[0]=wsum(simv[0]); simv[1]=wsum(simv[1]);
            if (lane==0){
                #pragma unroll
                for (int ke=0;ke<2;ke++){
                    float lg = cut[ke]*simv[ke];
                    g_logits[2*g+ke] = lg;
                    atomicMaxFloat(&g_maxv[srcs[ke]], lg);
                }
            }
        } else {
            #pragma unroll
            for (int ke=0;ke<2;ke++){
                float h = ke ? h1 : h0;
                float o[20];
                #pragma unroll
                for (int w=0;w<8;w++) o[w] = h*a0[ke][w];
                #pragma unroll
                for (int w=0;w<4;w++){
                    #pragma unroll
                    for (int m=0;m<3;m++)
                        o[8+w*3+m] = h*fmaf(s01[ke][w], Y[ke][m], v1[ke][w][m]);
                }
                #pragma unroll
                for (int j=0;j<20;j++) o[j]=wsum(o[j]);
                if (lane==0){
                    float4* vp = (float4*)(g_vals + (size_t)(2*g+ke)*20);
                    vp[0]=make_float4(o[0],o[1],o[2],o[3]);
                    vp[1]=make_float4(o[4],o[5],o[6],o[7]);
                    vp[2]=make_float4(o[8],o[9],o[10],o[11]);
                    vp[3]=make_float4(o[12],o[13],o[14],o[15]);
                    vp[4]=make_float4(o[16],o[17],o[18],o[19]);
                }
            }
        }
    }
}

// ---------------- kernel C: exp + denominator ----------------
__global__ void k_soft(const int* __restrict__ ei){
    int e = blockIdx.x*blockDim.x + threadIdx.x;
    if (e >= NE) return;
    int s = ei[e];
    float ex = expf(g_logits[e] - g_maxv[s]);
    g_logits[e] = ex;
    atomicAdd(&g_den[s], ex);
}

// ---------------- kernel D: attn, scatter to output ----------------
__global__ void k_out(const int* __restrict__ ei, float* __restrict__ out){
    int e = blockIdx.x*blockDim.x + threadIdx.x;
    if (e >= NE) return;
    int s = ei[e], d = ei[NE+e];
    float attn = g_logits[e] / g_den[s];
    float a = sqrtf(attn) * 0.03125f;     // /NUM_NEIGHBORS folded
    const float4* vp = (const float4*)(g_vals + (size_t)e*20);
    float* ob = out + (size_t)d*20;
    #pragma unroll
    for (int j=0;j<5;j++){
        float4 v = vp[j];
        atomicAdd(ob+j*4+0, a*v.x);
        atomicAdd(ob+j*4+1, a*v.y);
        atomicAdd(ob+j*4+2, a*v.z);
        atomicAdd(ob+j*4+3, a*v.w);
    }
}

extern "C" void kernel_launch(void* const* d_in, const int* in_sizes, int n_in,
                              void* d_out, int out_size)
{
    const float* x    = (const float*)d_in[0];
    const float* pos  = (const float*)d_in[1];
    const float* wq0  = (const float*)d_in[2];
    const float* wq1  = (const float*)d_in[3];
    const float* wkb1 = (const float*)d_in[4];
    const float* wkb2 = (const float*)d_in[5];
    const float* wvb1 = (const float*)d_in[6];
    const float* wvb2 = (const float*)d_in[7];
    const float* ws0  = (const float*)d_in[8];
    const float* ws1  = (const float*)d_in[9];
    const int*   ei   = (const int*)d_in[10];
    float* out = (float*)d_out;

    int smem = (32*580 + 32*33 + WARPS_B*288) * 4;
    cudaFuncSetAttribute(k_edge<true>,  cudaFuncAttributeMaxDynamicSharedMemorySize, smem);
    cudaFuncSetAttribute(k_edge<false>, cudaFuncAttributeMaxDynamicSharedMemorySize, smem);

    k_prep<<<(NN+255)/256, 256>>>(x, wq0, wq1, ws0, ws1, out);
    k_edge<true ><<<GRID_B, THREADS_B, smem>>>(x, pos, wkb1, wkb2, ei);
    k_edge<false><<<GRID_B, THREADS_B, smem>>>(x, pos, wvb1, wvb2, ei);
    k_soft<<<(NE+255)/256, 256>>>(ei);
    k_out <<<(NE+255)/256, 256>>>(ei, out);
}

// round 2
// speedup vs baseline: 1.2951x; 1.2951x over previous
#include <cuda_runtime.h>
#include <math.h>

#define NN 10000
#define NE 160000
#define EPI 6
#define NPAIR 3
#define WARPS 8
#define THREADS (WARPS*32)
#define GRID 148
#define NGROUP ((NE+EPI-1)/EPI)

// ---- smem layout (floats) ----
#define W2K_OFF 0
#define W2V_OFF (32*580)
#define W1K_OFF (2*32*580)
#define W1V_OFF (W1K_OFF+32*33)
#define FT_OFF  (W1V_OFF+32*33)
// per-warp feature block
#define FT_RB   0
#define FT_X0   256
#define FT_X1   512
#define FT_FD   896
#define FT_X1Q  1024
#define FT_QT0  1536
#define FT_QT1  1600
#define FT_QY   1696
#define FT_Y    1728
#define FT_CUT  1752
#define FT_SRC  1760
#define FT_SIZE 1776
#define SMEM_FLOATS (FT_OFF + WARPS*FT_SIZE)

typedef unsigned long long u64;

// ---------------- scratch ----------------
static __device__ float g_qt0[NN*8];
static __device__ float g_qt1[NN*12];
static __device__ float g_maxv[NN];
static __device__ float g_den[NN];
static __device__ float g_logits[NE];
static __device__ float g_vals[NE*20];

__device__ __forceinline__ void atomicMaxFloat(float* addr, float v){
    if (v >= 0.f) atomicMax((int*)addr, __float_as_int(v));
    else          atomicMin((unsigned int*)addr, __float_as_uint(v));
}

// ---- packed f32x2 helpers ----
__device__ __forceinline__ u64 dup2(float a){
    u64 r; asm("mov.b64 %0,{%1,%1};" : "=l"(r) : "f"(a)); return r;
}
__device__ __forceinline__ u64 pack2(float a, float b){
    u64 r; asm("mov.b64 %0,{%1,%2};" : "=l"(r) : "f"(a), "f"(b)); return r;
}
__device__ __forceinline__ void unpack2(u64 v, float& a, float& b){
    asm("mov.b64 {%0,%1},%2;" : "=f"(a), "=f"(b) : "l"(v));
}
__device__ __forceinline__ u64 fma2(u64 a, u64 b, u64 c){
    u64 d; asm("fma.rn.f32x2 %0,%1,%2,%3;" : "=l"(d) : "l"(a), "l"(b), "l"(c)); return d;
}
__device__ __forceinline__ u64 mul2(u64 a, u64 b){
    u64 d; asm("mul.rn.f32x2 %0,%1,%2;" : "=l"(d) : "l"(a), "l"(b)); return d;
}
__device__ __forceinline__ u64 wsum2(u64 v){
    #pragma unroll
    for (int o=16;o;o>>=1){
        u64 t = __shfl_down_sync(0xffffffffu, v, o);
        asm("add.rn.f32x2 %0,%0,%1;" : "+l"(v) : "l"(t));
    }
    return v;
}

// ---------------- kernel A: per-node query transform + init ----------------
__global__ void k_prep(const float* __restrict__ x,
                       const float* __restrict__ wq0, const float* __restrict__ wq1,
                       const float* __restrict__ ws0, const float* __restrict__ ws1,
                       float* __restrict__ out)
{
    int i = blockIdx.x*blockDim.x + threadIdx.x;
    if (i >= NN) return;
    const float* xr = x + (size_t)i*80;

    float q0[8];
    #pragma unroll
    for (int w=0;w<8;w++) q0[w]=0.f;
    #pragma unroll 4
    for (int u=0;u<32;u++){
        float xv = xr[u];
        #pragma unroll
        for (int w=0;w<8;w++) q0[w] = fmaf(xv, wq0[u*8+w], q0[w]);
    }
    #pragma unroll
    for (int w=0;w<8;w++) q0[w] *= 0.17677669529663687f;

    float q1[4][3];
    #pragma unroll
    for (int w=0;w<4;w++){ q1[w][0]=0.f; q1[w][1]=0.f; q1[w][2]=0.f; }
    #pragma unroll 4
    for (int u=0;u<16;u++){
        float xv0 = xr[32+u*3+0], xv1 = xr[32+u*3+1], xv2 = xr[32+u*3+2];
        #pragma unroll
        for (int w=0;w<4;w++){
            float wv = wq1[u*4+w];
            q1[w][0]=fmaf(xv0,wv,q1[w][0]);
            q1[w][1]=fmaf(xv1,wv,q1[w][1]);
            q1[w][2]=fmaf(xv2,wv,q1[w][2]);
        }
    }
    #pragma unroll
    for (int w=0;w<4;w++){ q1[w][0]*=0.25f; q1[w][1]*=0.25f; q1[w][2]*=0.25f; }

    const float CS  = 0.11180339887498949f;
    const float CS3 = 0.06454972243679028f;
    float qt0[8];
    #pragma unroll
    for (int v=0;v<8;v++) qt0[v]=0.f;
    #pragma unroll
    for (int u=0;u<8;u++){
        float qv = q0[u];
        #pragma unroll
        for (int v=0;v<8;v++) qt0[v] = fmaf(qv, ws0[u*8+v], qt0[v]);
    }
    float qt1[4][3];
    #pragma unroll
    for (int v=0;v<4;v++){ qt1[v][0]=0.f; qt1[v][1]=0.f; qt1[v][2]=0.f; }
    #pragma unroll
    for (int u=0;u<4;u++){
        #pragma unroll
        for (int v=0;v<4;v++){
            float wv = ws1[u*4+v];
            qt1[v][0]=fmaf(q1[u][0],wv,qt1[v][0]);
            qt1[v][1]=fmaf(q1[u][1],wv,qt1[v][1]);
            qt1[v][2]=fmaf(q1[u][2],wv,qt1[v][2]);
        }
    }
    #pragma unroll
    for (int v=0;v<8;v++) g_qt0[i*8+v] = CS * qt0[v];
    #pragma unroll
    for (int v=0;v<4;v++){
        g_qt1[i*12+v*3+0] = CS3*qt1[v][0];
        g_qt1[i*12+v*3+1] = CS3*qt1[v][1];
        g_qt1[i*12+v*3+2] = CS3*qt1[v][2];
    }
    g_maxv[i] = __int_as_float(0xff800000);
    g_den[i]  = 0.f;
    #pragma unroll
    for (int j=0;j<20;j++) out[i*20+j] = 0.f;
}

// ---- path A (0e weights, 32u) + path B (1o.1o->0e weights, 16u) ----
__device__ __forceinline__ void accumAB(const float* __restrict__ wr,
                                        const float* __restrict__ ft,
                                        u64 a0[NPAIR][8], u64 s01[NPAIR][4])
{
    #pragma unroll 8
    for (int u=0;u<32;u++){
        float4 wA = *(const float4*)(wr + u*8);
        float4 wB = *(const float4*)(wr + u*8 + 4);
        float4 wC = *(const float4*)(wr + 384 + u*4);
        ulonglong2 bp = *(const ulonglong2*)(ft + FT_X0 + u*8);
        u64 b2 = *(const u64*)(ft + FT_X0 + u*8 + 4);
        u64 wd[8] = {dup2(wA.x),dup2(wA.y),dup2(wA.z),dup2(wA.w),
                     dup2(wB.x),dup2(wB.y),dup2(wB.z),dup2(wB.w)};
        #pragma unroll
        for (int w=0;w<8;w++){
            a0[0][w]=fma2(wd[w],bp.x,a0[0][w]);
            a0[1][w]=fma2(wd[w],bp.y,a0[1][w]);
            a0[2][w]=fma2(wd[w],b2  ,a0[2][w]);
        }
        u64 cd[4]={dup2(wC.x),dup2(wC.y),dup2(wC.z),dup2(wC.w)};
        #pragma unroll
        for (int w=0;w<4;w++){
            s01[0][w]=fma2(cd[w],bp.x,s01[0][w]);
            s01[1][w]=fma2(cd[w],bp.y,s01[1][w]);
            s01[2][w]=fma2(cd[w],b2  ,s01[2][w]);
        }
    }
    #pragma unroll 8
    for (int u=0;u<16;u++){
        float4 wA = *(const float4*)(wr + 256 + u*8);
        float4 wB = *(const float4*)(wr + 256 + u*8 + 4);
        ulonglong2 bp = *(const ulonglong2*)(ft + FT_FD + u*8);
        u64 b2 = *(const u64*)(ft + FT_FD + u*8 + 4);
        u64 wd[8] = {dup2(wA.x),dup2(wA.y),dup2(wA.z),dup2(wA.w),
                     dup2(wB.x),dup2(wB.y),dup2(wB.z),dup2(wB.w)};
        #pragma unroll
        for (int w=0;w<8;w++){
            a0[0][w]=fma2(wd[w],bp.x,a0[0][w]);
            a0[1][w]=fma2(wd[w],bp.y,a0[1][w]);
            a0[2][w]=fma2(wd[w],b2  ,a0[2][w]);
        }
    }
}

// ---- path C for K (qt1 pre-folded into X1Q) ----
__device__ __forceinline__ void accumC_sim(const float* __restrict__ wr,
                                           const float* __restrict__ ft,
                                           u64 simc[NPAIR])
{
    #pragma unroll 8
    for (int u=0;u<16;u++){
        float4 wC = *(const float4*)(wr + 512 + u*4);
        u64 wd[4]={dup2(wC.x),dup2(wC.y),dup2(wC.z),dup2(wC.w)};
        #pragma unroll
        for (int w=0;w<4;w++){
            ulonglong2 bp = *(const ulonglong2*)(ft + FT_X1Q + (u*4+w)*8);
            u64 b2 = *(const u64*)(ft + FT_X1Q + (u*4+w)*8 + 4);
            simc[0]=fma2(wd[w],bp.x,simc[0]);
            simc[1]=fma2(wd[w],bp.y,simc[1]);
            simc[2]=fma2(wd[w],b2  ,simc[2]);
        }
    }
}

// ---- path C for V (full 1o output) ----
__device__ __forceinline__ void accumC_full(const float* __restrict__ wr,
                                            const float* __restrict__ ft,
                                            u64 v1[NPAIR][4][3])
{
    #pragma unroll 8
    for (int u=0;u<16;u++){
        float4 wC = *(const float4*)(wr + 512 + u*4);
        u64 wd[4]={dup2(wC.x),dup2(wC.y),dup2(wC.z),dup2(wC.w)};
        #pragma unroll
        for (int m=0;m<3;m++){
            ulonglong2 bp = *(const ulonglong2*)(ft + FT_X1 + (u*3+m)*8);
            u64 b2 = *(const u64*)(ft + FT_X1 + (u*3+m)*8 + 4);
            #pragma unroll
            for (int w=0;w<4;w++){
                v1[0][w][m]=fma2(wd[w],bp.x,v1[0][w][m]);
                v1[1][w][m]=fma2(wd[w],bp.y,v1[1][w][m]);
                v1[2][w][m]=fma2(wd[w],b2  ,v1[2][w][m]);
            }
        }
    }
}

// ---------------- fused edge kernel ----------------
__global__ void __launch_bounds__(THREADS, 1) k_edge(
    const float* __restrict__ x, const float* __restrict__ pos,
    const float* __restrict__ w1k_g, const float* __restrict__ w2k_g,
    const float* __restrict__ w1v_g, const float* __restrict__ w2v_g,
    const int* __restrict__ ei)
{
    extern __shared__ float sm[];
    const int tid = threadIdx.x, lane = tid & 31, wp = tid >> 5;

    // stage weights (scaled)
    for (int i=tid;i<32*32;i+=THREADS){
        sm[W1K_OFF + (i>>5)*33 + (i&31)] = w1k_g[i];
        sm[W1V_OFF + (i>>5)*33 + (i&31)] = w1v_g[i];
    }
    const float W2S = 0.02551551815399144f;  // 1/sqrt(48) * 1/sqrt(32)
    for (int i=tid;i<32*576;i+=THREADS){
        int h = i/576, o = i - h*576;
        sm[W2K_OFF + h*580 + o] = w2k_g[i]*W2S;
        sm[W2V_OFF + h*580 + o] = w2v_g[i]*W2S;
    }
    __syncthreads();

    float* ft = sm + FT_OFF + wp*FT_SIZE;
    int* sft = (int*)(ft + FT_SRC);
    const float* wrk = sm + W2K_OFF + lane*580;
    const float* wrv = sm + W2V_OFF + lane*580;

    for (int g = blockIdx.x*WARPS + wp; g < NGROUP; g += GRID*WARPS){
        const int base = g*EPI;
        __syncwarp();

        // ---- fill: per-edge geometry (lanes 0..5) ----
        float rr = 1.f; int sidx = 0;
        if (lane < EPI){
            int e = min(base+lane, NE-1);
            int s = ei[e], d = ei[NE+e];
            sidx = s;
            float vx = pos[3*s+0]-pos[3*d+0];
            float vy = pos[3*s+1]-pos[3*d+1];
            float vz = pos[3*s+2]-pos[3*d+2];
            float r2 = fmaf(vx,vx,fmaf(vy,vy,vz*vz)) + 1e-24f;
            float r  = sqrtf(r2);
            float ir = 1.f/r;
            rr = r;
            ft[FT_Y+0*8+lane] = 1.7320508075688772f*vx*ir;
            ft[FT_Y+1*8+lane] = 1.7320508075688772f*vy*ir;
            ft[FT_Y+2*8+lane] = 1.7320508075688772f*vz*ir;
            float t = 10.f*(1.f - r*0.4f);
            ft[FT_CUT+lane] = (t>0.f) ? expf(-1.f/fmaxf(t,1e-12f)) : 0.f;
            sft[lane] = s;
        }
        __syncwarp();

        // ---- fill: rb, x0, x1 ----
        #pragma unroll
        for (int ke=0; ke<EPI; ke++){
            float rk = __shfl_sync(0xffffffffu, rr, ke);
            int   sk = __shfl_sync(0xffffffffu, sidx, ke);
            float irk = 1.f/rk;
            ft[FT_RB + lane*8 + ke] =
                0.8944271909999159f * sinf((float)(lane+1)*1.2566370614359172f*rk) * irk;
            const float* xr = x + (size_t)sk*80;
            ft[FT_X0 + lane*8 + ke] = xr[lane];
            if (lane < 16){
                #pragma unroll
                for (int m=0;m<3;m++)
                    ft[FT_X1 + (lane*3+m)*8 + ke] = xr[32 + lane*3 + m];
            }
        }
        // ---- fill: stage qt0 / qt1 ----
        for (int id=lane; id<EPI*8; id+=32){
            int ke=id>>3, j=id&7;
            ft[FT_QT0 + j*8 + ke] = g_qt0[(size_t)sft[ke]*8 + j];
        }
        for (int id=lane; id<EPI*12; id+=32){
            int ke=id/12, j=id-ke*12;
            ft[FT_QT1 + j*8 + ke] = g_qt1[(size_t)sft[ke]*12 + j];
        }
        __syncwarp();

        // ---- fill: f1dY, X1Q, qY ----
        for (int id=lane; id<EPI*16; id+=32){
            int ke=id>>4, u=id&15;
            float v = (ft[FT_X1+(u*3+0)*8+ke]*ft[FT_Y+0*8+ke]
                     + ft[FT_X1+(u*3+1)*8+ke]*ft[FT_Y+1*8+ke]
                     + ft[FT_X1+(u*3+2)*8+ke]*ft[FT_Y+2*8+ke]) * 0.5773502691896258f;
            ft[FT_FD + u*8 + ke] = v;
        }
        for (int id=lane; id<EPI*64; id+=32){
            int ke=id>>6, u=(id>>2)&15, w=id&3;
            float v = ft[FT_X1+(u*3+0)*8+ke]*ft[FT_QT1+(w*3+0)*8+ke]
                    + ft[FT_X1+(u*3+1)*8+ke]*ft[FT_QT1+(w*3+1)*8+ke]
                    + ft[FT_X1+(u*3+2)*8+ke]*ft[FT_QT1+(w*3+2)*8+ke];
            ft[FT_X1Q + (u*4+w)*8 + ke] = v;
        }
        if (lane < EPI*4){
            int ke=lane>>2, w=lane&3;
            float v = ft[FT_QT1+(w*3+0)*8+ke]*ft[FT_Y+0*8+ke]
                    + ft[FT_QT1+(w*3+1)*8+ke]*ft[FT_Y+1*8+ke]
                    + ft[FT_QT1+(w*3+2)*8+ke]*ft[FT_Y+2*8+ke];
            ft[FT_QY + w*8 + ke] = v;
        }
        __syncwarp();

        // ---- hidden layer (both nets, packed pairs) ----
        u64 hk[NPAIR]={0,0,0}, hv[NPAIR]={0,0,0};
        #pragma unroll 8
        for (int i=0;i<32;i++){
            u64 wkd = dup2(sm[W1K_OFF + i*33 + lane]);
            u64 wvd = dup2(sm[W1V_OFF + i*33 + lane]);
            ulonglong2 rp = *(const ulonglong2*)(ft + FT_RB + i*8);
            u64 r2p = *(const u64*)(ft + FT_RB + i*8 + 4);
            hk[0]=fma2(wkd,rp.x,hk[0]); hk[1]=fma2(wkd,rp.y,hk[1]); hk[2]=fma2(wkd,r2p,hk[2]);
            hv[0]=fma2(wvd,rp.x,hv[0]); hv[1]=fma2(wvd,rp.y,hv[1]); hv[2]=fma2(wvd,r2p,hv[2]);
        }
        #pragma unroll
        for (int p=0;p<NPAIR;p++){
            float a,b;
            unpack2(hk[p],a,b);
            hk[p]=pack2(a/(1.f+expf(-a)), b/(1.f+expf(-b)));
            unpack2(hv[p],a,b);
            hv[p]=pack2(a/(1.f+expf(-a)), b/(1.f+expf(-b)));
        }

        // ---- K net ----
        {
            u64 a0[NPAIR][8], s01[NPAIR][4], simc[NPAIR];
            #pragma unroll
            for (int p=0;p<NPAIR;p++){
                simc[p]=0;
                #pragma unroll
                for (int w=0;w<8;w++) a0[p][w]=0;
                #pragma unroll
                for (int w=0;w<4;w++) s01[p][w]=0;
            }
            accumAB(wrk, ft, a0, s01);
            accumC_sim(wrk, ft, simc);
            #pragma unroll
            for (int p=0;p<NPAIR;p++){
                u64 s = simc[p];
                #pragma unroll
                for (int w=0;w<8;w++)
                    s = fma2(a0[p][w], *(const u64*)(ft+FT_QT0+w*8+2*p), s);
                #pragma unroll
                for (int w=0;w<4;w++)
                    s = fma2(s01[p][w], *(const u64*)(ft+FT_QY+w*8+2*p), s);
                s = mul2(s, hk[p]);
                s = wsum2(s);
                if (lane==0){
                    float s0,s1; unpack2(s,s0,s1);
                    int e0 = base+2*p, e1 = e0+1;
                    if (e0 < NE){
                        float lg = ft[FT_CUT+2*p]*s0;
                        g_logits[e0] = lg;
                        atomicMaxFloat(&g_maxv[sft[2*p]], lg);
                    }
                    if (e1 < NE){
                        float lg = ft[FT_CUT+2*p+1]*s1;
                        g_logits[e1] = lg;
                        atomicMaxFloat(&g_maxv[sft[2*p+1]], lg);
                    }
                }
            }
        }

        // ---- V net ----
        {
            u64 a0[NPAIR][8], s01[NPAIR][4], v1[NPAIR][4][3];
            #pragma unroll
            for (int p=0;p<NPAIR;p++){
                #pragma unroll
                for (int w=0;w<8;w++) a0[p][w]=0;
                #pragma unroll
                for (int w=0;w<4;w++){ s01[p][w]=0; v1[p][w][0]=0; v1[p][w][1]=0; v1[p][w][2]=0; }
            }
            accumAB(wrv, ft, a0, s01);
            accumC_full(wrv, ft, v1);
            #pragma unroll
            for (int p=0;p<NPAIR;p++){
                u64 o[20];
                #pragma unroll
                for (int w=0;w<8;w++) o[w] = mul2(hv[p], a0[p][w]);
                #pragma unroll
                for (int m=0;m<3;m++){
                    u64 Ym = *(const u64*)(ft + FT_Y + m*8 + 2*p);
                    #pragma unroll
                    for (int w=0;w<4;w++)
                        o[8+w*3+m] = mul2(hv[p], fma2(s01[p][w], Ym, v1[p][w][m]));
                }
                #pragma unroll
                for (int j=0;j<20;j++) o[j] = wsum2(o[j]);
                if (lane==0){
                    float lo[20], hi[20];
                    #pragma unroll
                    for (int j=0;j<20;j++) unpack2(o[j], lo[j], hi[j]);
                    int e0 = base+2*p, e1 = e0+1;
                    if (e0 < NE){
                        float4* vp = (float4*)(g_vals + (size_t)e0*20);
                        vp[0]=make_float4(lo[0],lo[1],lo[2],lo[3]);
                        vp[1]=make_float4(lo[4],lo[5],lo[6],lo[7]);
                        vp[2]=make_float4(lo[8],lo[9],lo[10],lo[11]);
                        vp[3]=make_float4(lo[12],lo[13],lo[14],lo[15]);
                        vp[4]=make_float4(lo[16],lo[17],lo[18],lo[19]);
                    }
                    if (e1 < NE){
                        float4* vp = (float4*)(g_vals + (size_t)e1*20);
                        vp[0]=make_float4(hi[0],hi[1],hi[2],hi[3]);
                        vp[1]=make_float4(hi[4],hi[5],hi[6],hi[7]);
                        vp[2]=make_float4(hi[8],hi[9],hi[10],hi[11]);
                        vp[3]=make_float4(hi[12],hi[13],hi[14],hi[15]);
                        vp[4]=make_float4(hi[16],hi[17],hi[18],hi[19]);
                    }
                }
            }
        }
    }
}

// ---------------- kernel C: exp + denominator ----------------
__global__ void k_soft(const int* __restrict__ ei){
    int e = blockIdx.x*blockDim.x + threadIdx.x;
    if (e >= NE) return;
    int s = ei[e];
    float ex = expf(g_logits[e] - g_maxv[s]);
    g_logits[e] = ex;
    atomicAdd(&g_den[s], ex);
}

// ---------------- kernel D: attn, scatter to output ----------------
__global__ void k_out(const int* __restrict__ ei, float* __restrict__ out){
    int e = blockIdx.x*blockDim.x + threadIdx.x;
    if (e >= NE) return;
    int s = ei[e], d = ei[NE+e];
    float attn = g_logits[e] / g_den[s];
    float a = sqrtf(attn) * 0.03125f;
    const float4* vp = (const float4*)(g_vals + (size_t)e*20);
    float* ob = out + (size_t)d*20;
    #pragma unroll
    for (int j=0;j<5;j++){
        float4 v = vp[j];
        asm volatile("red.global.add.v4.f32 [%0], {%1,%2,%3,%4};"
            :: "l"(ob+j*4), "f"(a*v.x), "f"(a*v.y), "f"(a*v.z), "f"(a*v.w) : "memory");
    }
}

extern "C" void kernel_launch(void* const* d_in, const int* in_sizes, int n_in,
                              void* d_out, int out_size)
{
    const float* x    = (const float*)d_in[0];
    const float* pos  = (const float*)d_in[1];
    const float* wq0  = (const float*)d_in[2];
    const float* wq1  = (const float*)d_in[3];
    const float* wkb1 = (const float*)d_in[4];
    const float* wkb2 = (const float*)d_in[5];
    const float* wvb1 = (const float*)d_in[6];
    const float* wvb2 = (const float*)d_in[7];
    const float* ws0  = (const float*)d_in[8];
    const float* ws1  = (const float*)d_in[9];
    const int*   ei   = (const int*)d_in[10];
    float* out = (float*)d_out;

    int smem = SMEM_FLOATS * 4;
    cudaFuncSetAttribute(k_edge, cudaFuncAttributeMaxDynamicSharedMemorySize, smem);

    k_prep<<<(NN+255)/256, 256>>>(x, wq0, wq1, ws0, ws1, out);
    k_edge<<<GRID, THREADS, smem>>>(x, pos, wkb1, wkb2, wvb1, wvb2, ei);
    k_soft<<<(NE+255)/256, 256>>>(ei);
    k_out <<<(NE+255)/256, 256>>>(ei, out);
}